// round 10
// baseline (speedup 1.0000x reference)
#include <cuda_runtime.h>
#include <cuda_bf16.h>
#include <cstdint>

#define B_USERS 2048
#define P_POSTS 16384
#define LEN     50
#define D_EMB   300
#define NFILT   100
#define HID     64
#define INF_    768

#define DC32    10              // ceil(304/32) k-chunks of 32 (K padded to 320)
#define QROWS   52              // 48 positions + max kk shift 4
#define QSTRIDE 84              // words per row (336 int8 >= 320); 84%32=20 -> ldsm conflict-free
#define QSZ     (QROWS * QSTRIDE)   // 4368 words per user per (hi|lo)

// weight frag counts: 13 n8 tiles per group, Kg kk, DC32 ksteps
#define FQ0     (13 * 3 * DC32)     // 390
#define FQ1     (13 * 4 * DC32)     // 520
#define FQ2     (13 * 5 * DC32)     // 650
#define NFQ     (FQ0 + FQ1 + FQ2)   // 1560

// ---------------- scratch (device globals; no allocation) ----------------
__device__ int    g_segstart[B_USERS + 1];
__device__ uint4  g_qhi4[(size_t)B_USERS * QSZ / 4];   // hist q_hi packed int8, conv layout
__device__ uint4  g_qlo4[(size_t)B_USERS * QSZ / 4];   // hist q_lo
__device__ float  g_sA[B_USERS * QROWS];               // per-row hist scale (s/127)
__device__ float  g_rec[B_USERS * HID];
__device__ uint4  g_wq[NFQ * 32];      // W frags: {hi_b0, hi_b1, lo_b0, lo_b1} int8-packed
__device__ float  g_swf[3 * 128];      // per-filter weight scale (t/127)
__device__ float  g_winv[3 * 128];     // 127/t
__device__ float  g_hwt[300 * 64];     // hist_w transposed [j][o]
__device__ float  g_w1t[INF_ * 128];   // fc_w1 transposed [d][o]
__device__ float  g_w2t[128 * 64];     // fc_w2 transposed [d][j]

// ---------------- job table: 8 warps, singles (g, nb); units 20/20/20/20/19/19/20/18 ----------------
__constant__ int8_t c_slots[8][6][2] = {
    {{2,0},{2,1},{2,2},{2,3},{-1,0},{-1,0}},
    {{2,4},{2,5},{2,6},{2,7},{-1,0},{-1,0}},
    {{2,8},{2,9},{2,10},{2,11},{-1,0},{-1,0}},
    {{2,12},{1,0},{1,1},{1,2},{0,0},{-1,0}},
    {{1,3},{1,4},{1,5},{1,6},{0,1},{-1,0}},
    {{1,7},{1,8},{1,9},{1,10},{0,2},{-1,0}},
    {{1,11},{1,12},{0,3},{0,4},{0,5},{0,6}},
    {{0,7},{0,8},{0,9},{0,10},{0,11},{0,12}},
};

#define MMA_S8(c, a, b0, b1)                                                    \
    asm("mma.sync.aligned.m16n8k32.row.col.s32.s8.s8.s32 "                      \
        "{%0,%1,%2,%3},{%4,%5,%6,%7},{%8,%9},{%0,%1,%2,%3};"                    \
        : "+r"(c[0]), "+r"(c[1]), "+r"(c[2]), "+r"(c[3])                         \
        : "r"(a[0]), "r"(a[1]), "r"(a[2]), "r"(a[3]), "r"(b0), "r"(b1))

__device__ __forceinline__ void ldsm4(uint32_t* r, const uint32_t* p) {
    uint32_t addr = (uint32_t)__cvta_generic_to_shared(p);
    asm volatile("ldmatrix.sync.aligned.m8n8.x4.shared.b16 {%0,%1,%2,%3}, [%4];"
                 : "=r"(r[0]), "=r"(r[1]), "=r"(r[2]), "=r"(r[3]) : "r"(addr));
}

__device__ __forceinline__ uint32_t pack_s8(int a, int b, int c, int d) {
    return (uint32_t)(a & 0xFF) | ((uint32_t)(b & 0xFF) << 8) |
           ((uint32_t)(c & 0xFF) << 16) | ((uint32_t)(d & 0xFF) << 24);
}

// ---------------- kernel A: segment offsets ----------------
__global__ void seg_bounds_kernel(const int* __restrict__ seg_ids) {
    int b = blockIdx.x * blockDim.x + threadIdx.x;
    if (b > B_USERS) return;
    int lo = 0, hi = P_POSTS;
    while (lo < hi) {
        int mid = (lo + hi) >> 1;
        if (seg_ids[mid] < b) lo = mid + 1; else hi = mid;
    }
    g_segstart[b] = lo;
}

// ---------------- kernel W0: per-filter weight max -> scales ----------------
__global__ void wscale_kernel(const float* __restrict__ w3, const float* __restrict__ w4,
                              const float* __restrict__ w5) {
    int wgid = blockIdx.x * 4 + (threadIdx.x >> 5);   // 0..299
    int lane = threadIdx.x & 31;
    if (wgid >= 300) return;
    int g = wgid / 100, f = wgid % 100;
    const float* w = (g == 0) ? w3 : ((g == 1) ? w4 : w5);
    int n = D_EMB * (3 + g);
    const float* wf = w + (size_t)f * n;
    float m = 0.f;
    for (int i = lane; i < n; i += 32) m = fmaxf(m, fabsf(__ldg(wf + i)));
#pragma unroll
    for (int off = 16; off > 0; off >>= 1)
        m = fmaxf(m, __shfl_xor_sync(0xffffffff, m, off));
    if (lane == 0) {
        g_swf[g * 128 + f]  = m * (1.f / 127.f);
        g_winv[g * 128 + f] = (m > 0.f) ? 127.f / m : 0.f;
    }
}

// ---------------- prep: int8 2-level W fragments + small transposes ----------------
__global__ void prep_kernel(const float* __restrict__ w3, const float* __restrict__ w4,
                            const float* __restrict__ w5, const float* __restrict__ hw_,
                            const float* __restrict__ w1, const float* __restrict__ w2) {
    int idx = blockIdx.x * 256 + threadIdx.x;
    if (idx < NFQ * 32) {
        int lane = idx & 31;
        int frag = idx >> 5;
        int g, Kg; const float* w; int rel;
        if (frag < FQ0)             { g = 0; Kg = 3; w = w3; rel = frag; }
        else if (frag < FQ0 + FQ1)  { g = 1; Kg = 4; w = w4; rel = frag - FQ0; }
        else                        { g = 2; Kg = 5; w = w5; rel = frag - FQ0 - FQ1; }
        int nb = rel / (Kg * DC32);
        int r2 = rel - nb * (Kg * DC32);
        int kk = r2 / DC32;
        int dc = r2 - kk * DC32;
        int n  = lane >> 2;
        int t  = lane & 3;
        int f  = nb * 8 + n;
        float inv = (f < NFILT) ? __ldg(g_winv + g * 128 + f) : 0.f;
        int ph[8], pl[8];
#pragma unroll
        for (int half = 0; half < 2; ++half) {
#pragma unroll
            for (int e = 0; e < 4; ++e) {
                int d = dc * 32 + half * 16 + 4 * t + e;
                float v = 0.f;
                if (f < NFILT && d < D_EMB)
                    v = __ldg(w + ((size_t)f * D_EMB + d) * Kg + kk);
                float vs = v * inv;
                int qh = __float2int_rn(vs);
                int ql = __float2int_rn((vs - (float)qh) * 128.f);
                ph[half * 4 + e] = qh;
                pl[half * 4 + e] = ql;
            }
        }
        uint4 out;
        out.x = pack_s8(ph[0], ph[1], ph[2], ph[3]);
        out.y = pack_s8(ph[4], ph[5], ph[6], ph[7]);
        out.z = pack_s8(pl[0], pl[1], pl[2], pl[3]);
        out.w = pack_s8(pl[4], pl[5], pl[6], pl[7]);
        g_wq[frag * 32 + lane] = out;
        return;
    }
    int i2 = idx - NFQ * 32;                   // g_hwt: 300*64
    if (i2 >= 0 && i2 < 300 * 64) {
        int o = i2 & 63; int j = i2 >> 6;
        g_hwt[i2] = __ldg(hw_ + o * 300 + j);
        return;
    }
    int i3 = i2 - 300 * 64;                    // g_w1t: 768*128
    if (i3 >= 0 && i3 < INF_ * 128) {
        int o = i3 & 127; int d = i3 >> 7;
        g_w1t[i3] = __ldg(w1 + o * INF_ + d);
        return;
    }
    int i4 = i3 - INF_ * 128;                  // g_w2t: 128*64
    if (i4 >= 0 && i4 < 128 * 64) {
        int j = i4 & 63; int d = i4 >> 6;
        g_w2t[i4] = __ldg(w2 + j * 128 + d);
    }
}

// ---------------- kernel B: segment-mean -> int8 2-level quantized rows ----------------
// grid = (52, B_USERS); 96 threads; t<75 compute 4 floats each.
__global__ void __launch_bounds__(96)
hist_kernel(const int* __restrict__ tokens, const float* __restrict__ emb) {
    __shared__ float wmax[3];
    int l = blockIdx.x;
    int b = blockIdx.y;
    int t = threadIdx.x;
    bool live = (l < LEN) && (t < 75);

    float x0 = 0.f, x1 = 0.f, x2 = 0.f, x3 = 0.f;
    if (live) {
        int s = g_segstart[b], e = g_segstart[b + 1];
        float4 a = {0.f, 0.f, 0.f, 0.f};
        float4 c = {0.f, 0.f, 0.f, 0.f};
        int p = s;
        for (; p + 3 < e; p += 4) {
            int t0 = __ldg(tokens + p * LEN + l);
            int t1 = __ldg(tokens + (p + 1) * LEN + l);
            int t2 = __ldg(tokens + (p + 2) * LEN + l);
            int t3 = __ldg(tokens + (p + 3) * LEN + l);
            float4 v0 = __ldg((const float4*)(emb + (size_t)t0 * D_EMB) + t);
            float4 v1 = __ldg((const float4*)(emb + (size_t)t1 * D_EMB) + t);
            float4 v2 = __ldg((const float4*)(emb + (size_t)t2 * D_EMB) + t);
            float4 v3 = __ldg((const float4*)(emb + (size_t)t3 * D_EMB) + t);
            a.x += v0.x + v2.x; a.y += v0.y + v2.y; a.z += v0.z + v2.z; a.w += v0.w + v2.w;
            c.x += v1.x + v3.x; c.y += v1.y + v3.y; c.z += v1.z + v3.z; c.w += v1.w + v3.w;
        }
        for (; p < e; ++p) {
            int t0 = __ldg(tokens + p * LEN + l);
            float4 v0 = __ldg((const float4*)(emb + (size_t)t0 * D_EMB) + t);
            a.x += v0.x; a.y += v0.y; a.z += v0.z; a.w += v0.w;
        }
        float sc = 1.0f / (float)max(e - s, 1);
        x0 = (a.x + c.x) * sc; x1 = (a.y + c.y) * sc;
        x2 = (a.z + c.z) * sc; x3 = (a.w + c.w) * sc;
    }

    // row max reduction over 96 threads (3 warps)
    float m = fmaxf(fmaxf(fabsf(x0), fabsf(x1)), fmaxf(fabsf(x2), fabsf(x3)));
#pragma unroll
    for (int off = 16; off > 0; off >>= 1)
        m = fmaxf(m, __shfl_xor_sync(0xffffffff, m, off));
    if ((t & 31) == 0) wmax[t >> 5] = m;
    __syncthreads();
    float s = fmaxf(wmax[0], fmaxf(wmax[1], wmax[2]));
    float inv = (s > 0.f) ? 127.f / s : 0.f;

    uint32_t* qhi = (uint32_t*)g_qhi4;
    uint32_t* qlo = (uint32_t*)g_qlo4;
    size_t base = (size_t)b * QSZ + l * QSTRIDE;
    if (t < QSTRIDE) {
        uint32_t wh = 0, wl = 0;
        if (live) {
            float v0 = x0 * inv, v1 = x1 * inv, v2 = x2 * inv, v3 = x3 * inv;
            int q0 = __float2int_rn(v0), q1 = __float2int_rn(v1);
            int q2 = __float2int_rn(v2), q3 = __float2int_rn(v3);
            int r0 = __float2int_rn((v0 - (float)q0) * 128.f);
            int r1 = __float2int_rn((v1 - (float)q1) * 128.f);
            int r2 = __float2int_rn((v2 - (float)q2) * 128.f);
            int r3 = __float2int_rn((v3 - (float)q3) * 128.f);
            wh = pack_s8(q0, q1, q2, q3);
            wl = pack_s8(r0, r1, r2, r3);
        }
        qhi[base + t] = wh;
        qlo[base + t] = wl;
    }
    if (t == 0) g_sA[b * QROWS + l] = (l < LEN) ? s * (1.f / 127.f) : 0.f;
}

// ---------------- conv job: int8 IMMA 2-level, one n8 tile (CNT=1) ----------------
__device__ __forceinline__ void conv_job(const uint32_t* __restrict__ sqh,
                                         const uint32_t* __restrict__ sql,
                                         const float* __restrict__ ssA,
                                         int g, int Kg, int gbase, int nb, int Tg,
                                         const float* __restrict__ bp,
                                         float* __restrict__ sf) {
    int lane = threadIdx.x & 31;
    int g8   = lane >> 2;
    int t    = lane & 3;
    int lr     = lane & 7;
    int sel    = lane >> 3;
    int rowsel = lr + ((sel & 1) << 3);
    int colsel = (sel & 2) << 1;

    float accf[3][4];
#pragma unroll
    for (int mt = 0; mt < 3; ++mt)
#pragma unroll
        for (int c = 0; c < 4; ++c) accf[mt][c] = 0.f;

    for (int kk = 0; kk < Kg; ++kk) {
        const uint4* fptr = g_wq + (size_t)(gbase + (nb * Kg + kk) * DC32) * 32 + lane;
        int rbase = kk + rowsel;
        int acc1[3][4], acc2[3][4];
#pragma unroll
        for (int mt = 0; mt < 3; ++mt)
#pragma unroll
            for (int c = 0; c < 4; ++c) { acc1[mt][c] = 0; acc2[mt][c] = 0; }

        uint4 wv = __ldg(fptr);
        for (int dc = 0; dc < DC32; ++dc) {
            uint4 wn;
            if (dc + 1 < DC32) wn = __ldg(fptr + (dc + 1) * 32);
            uint32_t ah[3][4], al[3][4];
            int widx = dc * 8 + colsel;
#pragma unroll
            for (int mt = 0; mt < 3; ++mt) {
                ldsm4(ah[mt], sqh + (mt * 16 + rbase) * QSTRIDE + widx);
                ldsm4(al[mt], sql + (mt * 16 + rbase) * QSTRIDE + widx);
            }
#pragma unroll
            for (int mt = 0; mt < 3; ++mt)
                MMA_S8(acc1[mt], ah[mt], wv.x, wv.y);   // q_hi * w_hi
#pragma unroll
            for (int mt = 0; mt < 3; ++mt)
                MMA_S8(acc2[mt], al[mt], wv.x, wv.y);   // q_lo * w_hi
#pragma unroll
            for (int mt = 0; mt < 3; ++mt)
                MMA_S8(acc2[mt], ah[mt], wv.z, wv.w);   // q_hi * w_lo
            wv = wn;
        }
        // per-kk rescale into fp32 (row scale depends on kk)
#pragma unroll
        for (int mt = 0; mt < 3; ++mt) {
            int r0 = mt * 16 + g8 + kk;
            float s0 = ssA[r0];
            float s1 = ssA[r0 + 8];
            accf[mt][0] += s0 * ((float)acc1[mt][0] + (float)acc2[mt][0] * 0.0078125f);
            accf[mt][1] += s0 * ((float)acc1[mt][1] + (float)acc2[mt][1] * 0.0078125f);
            accf[mt][2] += s1 * ((float)acc1[mt][2] + (float)acc2[mt][2] * 0.0078125f);
            accf[mt][3] += s1 * ((float)acc1[mt][3] + (float)acc2[mt][3] * 0.0078125f);
        }
    }

    // masked max-pool over positions, reduce across g8, apply filter scale + bias
    float m0 = -1e30f, m1 = -1e30f;
#pragma unroll
    for (int mt = 0; mt < 3; ++mt) {
        int p0 = mt * 16 + g8;
        int p1 = p0 + 8;
        if (p0 < Tg) { m0 = fmaxf(m0, accf[mt][0]); m1 = fmaxf(m1, accf[mt][1]); }
        if (p1 < Tg) { m0 = fmaxf(m0, accf[mt][2]); m1 = fmaxf(m1, accf[mt][3]); }
    }
#pragma unroll
    for (int off = 4; off < 32; off <<= 1) {
        m0 = fmaxf(m0, __shfl_xor_sync(0xffffffff, m0, off));
        m1 = fmaxf(m1, __shfl_xor_sync(0xffffffff, m1, off));
    }
    if (g8 == 0) {
        int f0 = nb * 8 + 2 * t;
        if (f0 < NFILT) {
            float sw = __ldg(g_swf + g * 128 + f0);
            sf[f0] = fmaxf(m0 * sw + __ldg(bp + f0), 0.f);
        }
        if (f0 + 1 < NFILT) {
            float sw = __ldg(g_swf + g * 128 + f0 + 1);
            sf[f0 + 1] = fmaxf(m1 * sw + __ldg(bp + f0 + 1), 0.f);
        }
    }
}

// ---------------- kernel C: TextCNN via int8 IMMA, 1 user / 256 thr / occ 3 ----------------
__global__ void __launch_bounds__(256, 3)
conv_mma_kernel(const float* __restrict__ b3, const float* __restrict__ b4,
                const float* __restrict__ b5, const float* __restrict__ hb_) {
    extern __shared__ uint32_t shw[];           // [qhi QSZ][qlo QSZ][sA 52][feats 304]
    float* ssA   = (float*)(shw + 2 * QSZ);
    float* feats = ssA + QROWS;
    int tid = threadIdx.x;
    int b   = blockIdx.x;

    {
        uint4* dhi = (uint4*)shw;
        uint4* dlo = (uint4*)(shw + QSZ);
        const uint4* shi4 = g_qhi4 + (size_t)b * (QSZ / 4);
        const uint4* slo4 = g_qlo4 + (size_t)b * (QSZ / 4);
        for (int i = tid; i < QSZ / 4; i += 256) {
            dhi[i] = __ldg(shi4 + i);
            dlo[i] = __ldg(slo4 + i);
        }
        if (tid < QROWS) ssA[tid] = g_sA[b * QROWS + tid];
    }
    __syncthreads();

    int slot = tid >> 5;
#pragma unroll
    for (int q = 0; q < 6; ++q) {
        int g  = c_slots[slot][q][0];
        if (g < 0) break;
        int nb = c_slots[slot][q][1];
        int Kg = 3 + g;
        int gbase = (g == 0) ? 0 : ((g == 1) ? FQ0 : (FQ0 + FQ1));
        int Tg = 51 - Kg;
        const float* bp = (g == 0) ? b3 : ((g == 1) ? b4 : b5);
        conv_job(shw, shw + QSZ, ssA, g, Kg, gbase, nb, Tg, bp, feats + g * 100);
    }
    __syncthreads();

    // rec GEMM: [300 feats] x [64 outs]
    if (tid < 64) {
        int o = tid;
        float r = __ldg(hb_ + o);
#pragma unroll 4
        for (int j = 0; j < 300; ++j)
            r = fmaf(feats[j], __ldg(g_hwt + j * HID + o), r);
        g_rec[b * HID + o] = r;
    }
}

// ---------------- kernel D: fc_out on root features + final add ----------------
#define TB 8
__global__ void __launch_bounds__(256)
fc_kernel(const float* __restrict__ x, const int* __restrict__ root,
          const float* __restrict__ b1, const float* __restrict__ b2,
          float* __restrict__ out) {
    __shared__ float sx[TB * INF_];
    __shared__ float hh[TB * 128];
    __shared__ int   ridx[TB];
    int tid = threadIdx.x;
    int b0 = blockIdx.x * TB;

    if (tid < TB) ridx[tid] = __ldg(root + b0 + tid);
    __syncthreads();
    for (int i = tid; i < TB * INF_; i += 256) {
        int u = i / INF_; int d = i - u * INF_;
        sx[i] = __ldg(x + (size_t)ridx[u] * INF_ + d);
    }
    __syncthreads();

    {
        int o  = tid & 127;
        int ug = tid >> 7;
        float acc[4] = {0.f, 0.f, 0.f, 0.f};
        for (int d = 0; d < INF_; ++d) {
            float wv = __ldg(g_w1t + d * 128 + o);
#pragma unroll
            for (int uu = 0; uu < 4; ++uu)
                acc[uu] = fmaf(sx[(ug * 4 + uu) * INF_ + d], wv, acc[uu]);
        }
        float bb = __ldg(b1 + o);
#pragma unroll
        for (int uu = 0; uu < 4; ++uu)
            hh[(ug * 4 + uu) * 128 + o] = fmaxf(acc[uu] + bb, 0.f);
    }
    __syncthreads();

    {
        int j = tid & 63;
        int q = tid >> 6;
        int u0 = 2 * q, u1 = 2 * q + 1;
        float a0 = 0.f, a1 = 0.f;
        for (int d = 0; d < 128; ++d) {
            float wv = __ldg(g_w2t + d * 64 + j);
            a0 = fmaf(hh[u0 * 128 + d], wv, a0);
            a1 = fmaf(hh[u1 * 128 + d], wv, a1);
        }
        float bb = __ldg(b2 + j);
        out[(b0 + u0) * HID + j] = a0 + bb + g_rec[(b0 + u0) * HID + j];
        out[(b0 + u1) * HID + j] = a1 + bb + g_rec[(b0 + u1) * HID + j];
    }
}

// ---------------- launch ----------------
extern "C" void kernel_launch(void* const* d_in, const int* in_sizes, int n_in,
                              void* d_out, int out_size) {
    const float* x        = (const float*)d_in[0];
    const int*   root     = (const int*)  d_in[1];
    const int*   tokens   = (const int*)  d_in[2];
    const int*   seg_ids  = (const int*)  d_in[3];
    const float* emb      = (const float*)d_in[4];
    const float* w3 = (const float*)d_in[5];   const float* b3 = (const float*)d_in[6];
    const float* w4 = (const float*)d_in[7];   const float* b4 = (const float*)d_in[8];
    const float* w5 = (const float*)d_in[9];   const float* b5 = (const float*)d_in[10];
    const float* hw = (const float*)d_in[11];  const float* hb = (const float*)d_in[12];
    const float* f1w = (const float*)d_in[13]; const float* f1b = (const float*)d_in[14];
    const float* f2w = (const float*)d_in[15]; const float* f2b = (const float*)d_in[16];
    float* out = (float*)d_out;

    const int conv_smem = (2 * QSZ + QROWS + 304) * (int)sizeof(uint32_t);  // ~35.5 KB
    cudaFuncSetAttribute(conv_mma_kernel, cudaFuncAttributeMaxDynamicSharedMemorySize,
                         conv_smem);

    int prep_threads = NFQ * 32 + 300 * 64 + INF_ * 128 + 128 * 64;
    seg_bounds_kernel<<<(B_USERS + 1 + 255) / 256, 256>>>(seg_ids);
    wscale_kernel<<<75, 128>>>(w3, w4, w5);
    prep_kernel<<<(prep_threads + 255) / 256, 256>>>(w3, w4, w5, hw, f1w, f2w);
    {
        dim3 grid(QROWS, B_USERS);               // 52 rows: 50 data + 2 pad
        hist_kernel<<<grid, 96>>>(tokens, emb);
    }
    conv_mma_kernel<<<B_USERS, 256, conv_smem>>>(b3, b4, b5, hb);
    fc_kernel<<<B_USERS / TB, 256>>>(x, root, f1b, f2b, out);
}

// round 11
// speedup vs baseline: 2.5416x; 2.5416x over previous
#include <cuda_runtime.h>
#include <cuda_bf16.h>
#include <cstdint>

#define B_USERS 2048
#define P_POSTS 16384
#define LEN     50
#define D_EMB   300
#define NFILT   100
#define HID     64
#define INF_    768

#define DC16    19             // ceil(300/16) k-chunks of 16
#define WROWS   52             // 48 positions + max kk shift 4
#define WSTRIDE 156            // words per row; 156%32=28 -> ldmatrix conflict-free
#define USZ     (WROWS * WSTRIDE)   // 8112 words per user per (hi|lo)

// fragment counts (13 n8 tiles per group)
#define FRG0    (13 * 3 * DC16)     // 741
#define FRG1    (13 * 4 * DC16)     // 988
#define FRG2    (13 * 5 * DC16)     // 1235
#define NFRAG   (FRG0 + FRG1 + FRG2)  // 2964

// ---------------- scratch (device globals; no allocation) ----------------
__device__ int    g_segstart[B_USERS + 1];
__device__ uint4  g_hhi[(size_t)B_USERS * USZ / 4];   // packed bf16 hi, conv layout
__device__ uint4  g_hlo[(size_t)B_USERS * USZ / 4];   // packed bf16 lo
__device__ float  g_rec[B_USERS * HID];
__device__ uint4  g_wf[NFRAG * 32];     // W frags: {hi_b0, hi_b1, lo_b0, lo_b1} per lane
__device__ float  g_hwt[300 * 64];      // hist_w transposed [j][o]
__device__ float  g_w1t[INF_ * 128];    // fc_w1 transposed [d][o]
__device__ float  g_w2t[128 * 64];      // fc_w2 transposed [d][j]

// ---------------- job table: 8 warps, cnt<=2 ----------------
struct Job { int8_t g, nb0, cnt; };
__constant__ Job c_slots[8][4] = {
    {{2, 0,2},{2, 2,2},{-1,0,0},{-1,0,0}},
    {{2, 4,2},{2, 6,2},{-1,0,0},{-1,0,0}},
    {{2, 8,2},{2,10,2},{-1,0,0},{-1,0,0}},
    {{2,12,1},{1, 0,2},{0, 0,2},{-1,0,0}},
    {{1, 2,2},{1, 4,2},{0, 2,1},{-1,0,0}},
    {{1, 6,2},{1, 8,2},{0, 3,1},{-1,0,0}},
    {{1,10,2},{1,12,1},{0, 4,2},{0, 6,1}},
    {{0, 7,2},{0, 9,2},{0,11,2},{-1,0,0}},
};

__device__ __forceinline__ uint32_t pack_bf16(float a, float b) {
    __nv_bfloat16 ha = __float2bfloat16_rn(a);
    __nv_bfloat16 hb = __float2bfloat16_rn(b);
    return ((uint32_t)__bfloat16_as_ushort(hb) << 16) | __bfloat16_as_ushort(ha);
}

#define MMA_BF16(c, a, b0, b1)                                                  \
    asm("mma.sync.aligned.m16n8k16.row.col.f32.bf16.bf16.f32 "                  \
        "{%0,%1,%2,%3},{%4,%5,%6,%7},{%8,%9},{%0,%1,%2,%3};"                    \
        : "+f"(c[0]), "+f"(c[1]), "+f"(c[2]), "+f"(c[3])                         \
        : "r"(a[0]), "r"(a[1]), "r"(a[2]), "r"(a[3]), "r"(b0), "r"(b1))

__device__ __forceinline__ void ldsm4(uint32_t* r, const uint32_t* p) {
    uint32_t addr = (uint32_t)__cvta_generic_to_shared(p);
    asm volatile("ldmatrix.sync.aligned.m8n8.x4.shared.b16 {%0,%1,%2,%3}, [%4];"
                 : "=r"(r[0]), "=r"(r[1]), "=r"(r[2]), "=r"(r[3]) : "r"(addr));
}

// ---------------- kernel A: segment offsets ----------------
__global__ void seg_bounds_kernel(const int* __restrict__ seg_ids) {
    int b = blockIdx.x * blockDim.x + threadIdx.x;
    if (b > B_USERS) return;
    int lo = 0, hi = P_POSTS;
    while (lo < hi) {
        int mid = (lo + hi) >> 1;
        if (seg_ids[mid] < b) lo = mid + 1; else hi = mid;
    }
    g_segstart[b] = lo;
}

// ---------------- prep: bf16 hi/lo W fragments + small transposes ----------------
__global__ void prep_kernel(const float* __restrict__ w3, const float* __restrict__ w4,
                            const float* __restrict__ w5, const float* __restrict__ hw_,
                            const float* __restrict__ w1, const float* __restrict__ w2) {
    int idx = blockIdx.x * 256 + threadIdx.x;
    if (idx < NFRAG * 32) {
        int lane = idx & 31;
        int frag = idx >> 5;
        int Kg; const float* w; int rel;
        if (frag < FRG0)               { Kg = 3; w = w3; rel = frag; }
        else if (frag < FRG0 + FRG1)   { Kg = 4; w = w4; rel = frag - FRG0; }
        else                           { Kg = 5; w = w5; rel = frag - FRG0 - FRG1; }
        int nb = rel / (Kg * DC16);
        int r2 = rel - nb * (Kg * DC16);
        int kk = r2 / DC16;
        int dc = r2 - kk * DC16;
        int n  = lane >> 2;
        int t  = lane & 3;
        int f  = nb * 8 + n;
        float v[4] = {0.f, 0.f, 0.f, 0.f};
        int dk[4] = {2*t, 2*t+1, 2*t+8, 2*t+9};
        if (f < NFILT) {
#pragma unroll
            for (int e = 0; e < 4; ++e) {
                int d = dc * 16 + dk[e];
                if (d < D_EMB) v[e] = __ldg(w + (f * D_EMB + d) * Kg + kk);
            }
        }
        float h[4], l[4];
#pragma unroll
        for (int e = 0; e < 4; ++e) {
            __nv_bfloat16 hb = __float2bfloat16_rn(v[e]);
            h[e] = __bfloat162float(hb);
            l[e] = v[e] - h[e];
        }
        uint4 out;
        out.x = pack_bf16(h[0], h[1]);
        out.y = pack_bf16(h[2], h[3]);
        out.z = pack_bf16(l[0], l[1]);
        out.w = pack_bf16(l[2], l[3]);
        g_wf[frag * 32 + lane] = out;
        return;
    }
    int i2 = idx - NFRAG * 32;                 // g_hwt: 300*64
    if (i2 >= 0 && i2 < 300 * 64) {
        int o = i2 & 63; int j = i2 >> 6;
        g_hwt[i2] = __ldg(hw_ + o * 300 + j);
        return;
    }
    int i3 = i2 - 300 * 64;                    // g_w1t: 768*128
    if (i3 >= 0 && i3 < INF_ * 128) {
        int o = i3 & 127; int d = i3 >> 7;
        g_w1t[i3] = __ldg(w1 + o * INF_ + d);
        return;
    }
    int i4 = i3 - INF_ * 128;                  // g_w2t: 128*64
    if (i4 >= 0 && i4 < 128 * 64) {
        int j = i4 & 63; int d = i4 >> 6;
        g_w2t[i4] = __ldg(w2 + j * 128 + d);
    }
}

// ---------------- kernel B: segment-mean -> packed bf16 hi/lo, conv layout ----------------
// grid = (52, B_USERS): rows 50,51 are pad (zeroed). 96 threads; t<75 compute.
__global__ void __launch_bounds__(96)
hist_kernel(const int* __restrict__ tokens, const float* __restrict__ emb) {
    int l = blockIdx.x;
    int b = blockIdx.y;
    int t = threadIdx.x;
    uint2* hhi = (uint2*)g_hhi;
    uint2* hlo = (uint2*)g_hlo;
    size_t rowbase = ((size_t)b * USZ + l * WSTRIDE) >> 1;   // uint2 index

    if (l >= LEN) {                            // pad rows: zero all 156 words
        if (t < WSTRIDE / 2) {
            hhi[rowbase + t] = make_uint2(0u, 0u);
            hlo[rowbase + t] = make_uint2(0u, 0u);
        }
        return;
    }
    if (t >= 75) {                             // pad words 150..155
        if (t < 78) {
            hhi[rowbase + t] = make_uint2(0u, 0u);
            hlo[rowbase + t] = make_uint2(0u, 0u);
        }
        return;
    }

    int s = g_segstart[b], e = g_segstart[b + 1];
    float4 a = {0.f, 0.f, 0.f, 0.f};
    float4 c = {0.f, 0.f, 0.f, 0.f};
    int p = s;
    for (; p + 3 < e; p += 4) {
        int t0 = __ldg(tokens + p * LEN + l);
        int t1 = __ldg(tokens + (p + 1) * LEN + l);
        int t2 = __ldg(tokens + (p + 2) * LEN + l);
        int t3 = __ldg(tokens + (p + 3) * LEN + l);
        float4 v0 = __ldg((const float4*)(emb + (size_t)t0 * D_EMB) + t);
        float4 v1 = __ldg((const float4*)(emb + (size_t)t1 * D_EMB) + t);
        float4 v2 = __ldg((const float4*)(emb + (size_t)t2 * D_EMB) + t);
        float4 v3 = __ldg((const float4*)(emb + (size_t)t3 * D_EMB) + t);
        a.x += v0.x + v2.x; a.y += v0.y + v2.y; a.z += v0.z + v2.z; a.w += v0.w + v2.w;
        c.x += v1.x + v3.x; c.y += v1.y + v3.y; c.z += v1.z + v3.z; c.w += v1.w + v3.w;
    }
    for (; p < e; ++p) {
        int t0 = __ldg(tokens + p * LEN + l);
        float4 v0 = __ldg((const float4*)(emb + (size_t)t0 * D_EMB) + t);
        a.x += v0.x; a.y += v0.y; a.z += v0.z; a.w += v0.w;
    }
    float sc = 1.0f / (float)max(e - s, 1);
    float x0 = (a.x + c.x) * sc, x1 = (a.y + c.y) * sc;
    float x2 = (a.z + c.z) * sc, x3 = (a.w + c.w) * sc;

    __nv_bfloat16 h0 = __float2bfloat16_rn(x0), h1 = __float2bfloat16_rn(x1);
    __nv_bfloat16 h2 = __float2bfloat16_rn(x2), h3 = __float2bfloat16_rn(x3);
    uint2 whi, wlo;
    whi.x = ((uint32_t)__bfloat16_as_ushort(h1) << 16) | __bfloat16_as_ushort(h0);
    whi.y = ((uint32_t)__bfloat16_as_ushort(h3) << 16) | __bfloat16_as_ushort(h2);
    wlo.x = pack_bf16(x0 - __bfloat162float(h0), x1 - __bfloat162float(h1));
    wlo.y = pack_bf16(x2 - __bfloat162float(h2), x3 - __bfloat162float(h3));
    hhi[rowbase + t] = whi;
    hlo[rowbase + t] = wlo;
}

// ---------------- conv job: prefetched weights + ldmatrix + pass-major bf16x3 ----------------
template <int CNT>
__device__ __forceinline__ void conv_job(const uint32_t* __restrict__ shi,
                                         const uint32_t* __restrict__ slo,
                                         int Kg, int gbase, int nb0, int Tg,
                                         const float* __restrict__ bp,
                                         float* __restrict__ sf) {
    int lane = threadIdx.x & 31;
    int g8   = lane >> 2;
    int t    = lane & 3;
    int lr     = lane & 7;
    int sel    = lane >> 3;
    int rowsel = lr + ((sel & 1) << 3);
    int colsel = (sel & 2) << 1;

    float acc[3][CNT][4];
#pragma unroll
    for (int mt = 0; mt < 3; ++mt)
#pragma unroll
        for (int j = 0; j < CNT; ++j)
#pragma unroll
            for (int c = 0; c < 4; ++c) acc[mt][j][c] = 0.f;

    for (int kk = 0; kk < Kg; ++kk) {
        const uint4* fptr = g_wf + (size_t)(gbase + (nb0 * Kg + kk) * DC16) * 32 + lane;
        const size_t jstride = (size_t)(Kg * DC16) * 32;
        int rbase = kk + rowsel;
        uint4 wv[CNT];
#pragma unroll
        for (int j = 0; j < CNT; ++j) wv[j] = __ldg(fptr + j * jstride);

        for (int dc = 0; dc < DC16; ++dc) {
            uint4 wn[CNT];
            if (dc + 1 < DC16) {
#pragma unroll
                for (int j = 0; j < CNT; ++j)
                    wn[j] = __ldg(fptr + j * jstride + (dc + 1) * 32);
            }
            uint32_t ah[3][4], al[3][4];
            int widx = dc * 8 + colsel;
#pragma unroll
            for (int mt = 0; mt < 3; ++mt) {
                const uint32_t* pa = shi + (mt * 16 + rbase) * WSTRIDE + widx;
                const uint32_t* pl = slo + (mt * 16 + rbase) * WSTRIDE + widx;
                ldsm4(ah[mt], pa);
                ldsm4(al[mt], pl);
            }
#pragma unroll
            for (int j = 0; j < CNT; ++j)
#pragma unroll
                for (int mt = 0; mt < 3; ++mt)
                    MMA_BF16(acc[mt][j], ah[mt], wv[j].x, wv[j].y);   // hi*hi
#pragma unroll
            for (int j = 0; j < CNT; ++j)
#pragma unroll
                for (int mt = 0; mt < 3; ++mt)
                    MMA_BF16(acc[mt][j], ah[mt], wv[j].z, wv[j].w);   // hi*lo
#pragma unroll
            for (int j = 0; j < CNT; ++j)
#pragma unroll
                for (int mt = 0; mt < 3; ++mt)
                    MMA_BF16(acc[mt][j], al[mt], wv[j].x, wv[j].y);   // lo*hi
#pragma unroll
            for (int j = 0; j < CNT; ++j) wv[j] = wn[j];
        }
    }

#pragma unroll
    for (int j = 0; j < CNT; ++j) {
        float m0 = -1e30f, m1 = -1e30f;
#pragma unroll
        for (int mt = 0; mt < 3; ++mt) {
            int p0 = mt * 16 + g8;
            int p1 = p0 + 8;
            if (p0 < Tg) { m0 = fmaxf(m0, acc[mt][j][0]); m1 = fmaxf(m1, acc[mt][j][1]); }
            if (p1 < Tg) { m0 = fmaxf(m0, acc[mt][j][2]); m1 = fmaxf(m1, acc[mt][j][3]); }
        }
#pragma unroll
        for (int off = 4; off < 32; off <<= 1) {
            m0 = fmaxf(m0, __shfl_xor_sync(0xffffffff, m0, off));
            m1 = fmaxf(m1, __shfl_xor_sync(0xffffffff, m1, off));
        }
        if (g8 == 0) {
            int f0 = (nb0 + j) * 8 + 2 * t;
            if (f0 < NFILT)     sf[f0]     = fmaxf(m0 + __ldg(bp + f0), 0.f);
            if (f0 + 1 < NFILT) sf[f0 + 1] = fmaxf(m1 + __ldg(bp + f0 + 1), 0.f);
        }
    }
}

__device__ __forceinline__ void run_job(const uint32_t* shi, const uint32_t* slo,
                                        int g, int nb0, int cnt,
                                        const float* b3, const float* b4,
                                        const float* b5, float* feats_u) {
    int Kg = 3 + g;
    int gbase = (g == 0) ? 0 : ((g == 1) ? FRG0 : (FRG0 + FRG1));
    int Tg = 51 - Kg;
    const float* bp = (g == 0) ? b3 : ((g == 1) ? b4 : b5);
    float* sf = feats_u + g * 100;
    if (cnt == 2) conv_job<2>(shi, slo, Kg, gbase, nb0, Tg, bp, sf);
    else          conv_job<1>(shi, slo, Kg, gbase, nb0, Tg, bp, sf);
}

// ---------------- kernel C: TextCNN via bf16x3 tensor cores, 1 user / 256 thr ----------------
__global__ void __launch_bounds__(256, 3)
conv_mma_kernel(const float* __restrict__ b3, const float* __restrict__ b4,
                const float* __restrict__ b5, const float* __restrict__ hb_) {
    extern __shared__ uint32_t shw[];           // [hi USZ][lo USZ][feats 304]
    float* feats = (float*)(shw + 2 * USZ);
    int tid = threadIdx.x;
    int b   = blockIdx.x;

    // straight copy: hist already packed in conv layout
    {
        uint4* dhi = (uint4*)shw;
        uint4* dlo = (uint4*)(shw + USZ);
        const uint4* shi4 = g_hhi + (size_t)b * (USZ / 4);
        const uint4* slo4 = g_hlo + (size_t)b * (USZ / 4);
        for (int i = tid; i < USZ / 4; i += 256) {
            dhi[i] = __ldg(shi4 + i);
            dlo[i] = __ldg(slo4 + i);
        }
    }
    __syncthreads();

    int slot = tid >> 5;
    const uint32_t* shi = shw;
    const uint32_t* slo = shw + USZ;

#pragma unroll
    for (int q = 0; q < 4; ++q) {
        Job jb = c_slots[slot][q];
        if (jb.g < 0) continue;
        run_job(shi, slo, jb.g, jb.nb0, jb.cnt, b3, b4, b5, feats);
    }
    __syncthreads();

    // rec GEMM: [300 feats] x [64 outs]
    if (tid < 64) {
        int o = tid;
        float r = __ldg(hb_ + o);
#pragma unroll 4
        for (int j = 0; j < 300; ++j)
            r = fmaf(feats[j], __ldg(g_hwt + j * HID + o), r);
        g_rec[b * HID + o] = r;
    }
}

// ---------------- kernel D: fc_out on root features + final add (TB=16) ----------------
#define TB 16
__global__ void __launch_bounds__(256)
fc_kernel(const float* __restrict__ x, const int* __restrict__ root,
          const float* __restrict__ b1, const float* __restrict__ b2,
          float* __restrict__ out) {
    extern __shared__ float fsm[];           // [TB*INF_ sx][TB*128 hh][TB ridx]
    float* sx = fsm;
    float* hh = fsm + TB * INF_;
    int*   ridx = (int*)(hh + TB * 128);
    int tid = threadIdx.x;
    int b0 = blockIdx.x * TB;

    if (tid < TB) ridx[tid] = __ldg(root + b0 + tid);
    __syncthreads();
    for (int i = tid; i < TB * INF_; i += 256) {
        int u = i / INF_; int d = i - u * INF_;
        sx[i] = __ldg(x + (size_t)ridx[u] * INF_ + d);
    }
    __syncthreads();

    // layer 1: h[u][o] = relu(x_u . w1[o] + b1[o]);  o = tid&127, 8 users per thread
    {
        int o  = tid & 127;
        int ug = tid >> 7;                   // 0/1 -> users [ug*8, ug*8+8)
        float acc[8] = {0.f,0.f,0.f,0.f,0.f,0.f,0.f,0.f};
        for (int d = 0; d < INF_; ++d) {
            float wv = __ldg(g_w1t + d * 128 + o);   // lane-coalesced
#pragma unroll
            for (int uu = 0; uu < 8; ++uu)
                acc[uu] = fmaf(sx[(ug * 8 + uu) * INF_ + d], wv, acc[uu]);
        }
        float bb = __ldg(b1 + o);
#pragma unroll
        for (int uu = 0; uu < 8; ++uu)
            hh[(ug * 8 + uu) * 128 + o] = fmaxf(acc[uu] + bb, 0.f);
    }
    __syncthreads();

    // layer 2: out[u][j] = h_u . w2[j] + b2[j] + rec;  j = tid&63, 4 users per thread
    {
        int j = tid & 63;
        int q = tid >> 6;                    // 0..3 -> users [q*4, q*4+4)
        float a0 = 0.f, a1 = 0.f, a2 = 0.f, a3 = 0.f;
        for (int d = 0; d < 128; ++d) {
            float wv = __ldg(g_w2t + d * 64 + j);    // lane-coalesced
            a0 = fmaf(hh[(q * 4 + 0) * 128 + d], wv, a0);
            a1 = fmaf(hh[(q * 4 + 1) * 128 + d], wv, a1);
            a2 = fmaf(hh[(q * 4 + 2) * 128 + d], wv, a2);
            a3 = fmaf(hh[(q * 4 + 3) * 128 + d], wv, a3);
        }
        float bb = __ldg(b2 + j);
        out[(b0 + q * 4 + 0) * HID + j] = a0 + bb + g_rec[(b0 + q * 4 + 0) * HID + j];
        out[(b0 + q * 4 + 1) * HID + j] = a1 + bb + g_rec[(b0 + q * 4 + 1) * HID + j];
        out[(b0 + q * 4 + 2) * HID + j] = a2 + bb + g_rec[(b0 + q * 4 + 2) * HID + j];
        out[(b0 + q * 4 + 3) * HID + j] = a3 + bb + g_rec[(b0 + q * 4 + 3) * HID + j];
    }
}

// ---------------- launch ----------------
extern "C" void kernel_launch(void* const* d_in, const int* in_sizes, int n_in,
                              void* d_out, int out_size) {
    const float* x        = (const float*)d_in[0];
    const int*   root     = (const int*)  d_in[1];
    const int*   tokens   = (const int*)  d_in[2];
    const int*   seg_ids  = (const int*)  d_in[3];
    const float* emb      = (const float*)d_in[4];
    const float* w3 = (const float*)d_in[5];   const float* b3 = (const float*)d_in[6];
    const float* w4 = (const float*)d_in[7];   const float* b4 = (const float*)d_in[8];
    const float* w5 = (const float*)d_in[9];   const float* b5 = (const float*)d_in[10];
    const float* hw = (const float*)d_in[11];  const float* hb = (const float*)d_in[12];
    const float* f1w = (const float*)d_in[13]; const float* f1b = (const float*)d_in[14];
    const float* f2w = (const float*)d_in[15]; const float* f2b = (const float*)d_in[16];
    float* out = (float*)d_out;

    const int conv_smem = (2 * USZ + 304) * (int)sizeof(uint32_t);  // ~66.1 KB
    cudaFuncSetAttribute(conv_mma_kernel, cudaFuncAttributeMaxDynamicSharedMemorySize,
                         conv_smem);
    const int fc_smem = (TB * INF_ + TB * 128 + TB) * (int)sizeof(float);  // ~57.4 KB
    cudaFuncSetAttribute(fc_kernel, cudaFuncAttributeMaxDynamicSharedMemorySize,
                         fc_smem);

    int prep_threads = NFRAG * 32 + 300 * 64 + INF_ * 128 + 128 * 64;
    seg_bounds_kernel<<<(B_USERS + 1 + 255) / 256, 256>>>(seg_ids);
    prep_kernel<<<(prep_threads + 255) / 256, 256>>>(w3, w4, w5, hw, f1w, f2w);
    {
        dim3 grid(WROWS, B_USERS);               // 52 rows: 50 data + 2 pad
        hist_kernel<<<grid, 96>>>(tokens, emb);
    }
    conv_mma_kernel<<<B_USERS, 256, conv_smem>>>(b3, b4, b5, hb);
    fc_kernel<<<B_USERS / TB, 256, fc_smem>>>(x, root, f1b, f2b, out);
}

// round 12
// speedup vs baseline: 3.3886x; 1.3332x over previous
#include <cuda_runtime.h>
#include <cuda_bf16.h>
#include <cuda_fp16.h>
#include <cstdint>

#define B_USERS 2048
#define P_POSTS 16384
#define LEN     50
#define D_EMB   300
#define NFILT   100
#define HID     64
#define INF_    768

#define DC16    19             // ceil(300/16) k-chunks of 16
#define WROWS   52             // 48 positions + max kk shift 4
#define WSTRIDE 156            // words per row; 156%32=28 -> ldmatrix conflict-free
#define USZ     (WROWS * WSTRIDE)   // 8112 words per user

// fragment counts (13 n8 tiles per group)
#define FRG0    (13 * 3 * DC16)     // 741
#define FRG1    (13 * 4 * DC16)     // 988
#define FRG2    (13 * 5 * DC16)     // 1235
#define NFRAG   (FRG0 + FRG1 + FRG2)  // 2964

// ---------------- scratch (device globals; no allocation) ----------------
__device__ int    g_segstart[B_USERS + 1];
__device__ uint4  g_hq[(size_t)B_USERS * USZ / 4];    // packed fp16 hist, conv layout
__device__ float  g_rec[B_USERS * HID];
__device__ uint2  g_wf[NFRAG * 32];     // W frags: {b0, b1} fp16x2 per lane
__device__ float  g_hwt[300 * 64];      // hist_w transposed [j][o]
__device__ float  g_w1t[INF_ * 128];    // fc_w1 transposed [d][o]
__device__ float  g_w2t[128 * 64];      // fc_w2 transposed [d][j]

// ---------------- job table: 8 warps, cnt<=2 ----------------
struct Job { int8_t g, nb0, cnt; };
__constant__ Job c_slots[8][4] = {
    {{2, 0,2},{2, 2,2},{-1,0,0},{-1,0,0}},
    {{2, 4,2},{2, 6,2},{-1,0,0},{-1,0,0}},
    {{2, 8,2},{2,10,2},{-1,0,0},{-1,0,0}},
    {{2,12,1},{1, 0,2},{0, 0,2},{-1,0,0}},
    {{1, 2,2},{1, 4,2},{0, 2,1},{-1,0,0}},
    {{1, 6,2},{1, 8,2},{0, 3,1},{-1,0,0}},
    {{1,10,2},{1,12,1},{0, 4,2},{0, 6,1}},
    {{0, 7,2},{0, 9,2},{0,11,2},{-1,0,0}},
};

__device__ __forceinline__ uint32_t pack_h2(float a, float b) {
    __half ha = __float2half_rn(a);
    __half hb = __float2half_rn(b);
    return ((uint32_t)__half_as_ushort(hb) << 16) | __half_as_ushort(ha);
}

#define MMA_F16(c, a, b0, b1)                                                   \
    asm("mma.sync.aligned.m16n8k16.row.col.f32.f16.f16.f32 "                    \
        "{%0,%1,%2,%3},{%4,%5,%6,%7},{%8,%9},{%0,%1,%2,%3};"                    \
        : "+f"(c[0]), "+f"(c[1]), "+f"(c[2]), "+f"(c[3])                         \
        : "r"(a[0]), "r"(a[1]), "r"(a[2]), "r"(a[3]), "r"(b0), "r"(b1))

__device__ __forceinline__ void ldsm4(uint32_t* r, const uint32_t* p) {
    uint32_t addr = (uint32_t)__cvta_generic_to_shared(p);
    asm volatile("ldmatrix.sync.aligned.m8n8.x4.shared.b16 {%0,%1,%2,%3}, [%4];"
                 : "=r"(r[0]), "=r"(r[1]), "=r"(r[2]), "=r"(r[3]) : "r"(addr));
}

// ---------------- kernel A: segment offsets ----------------
__global__ void seg_bounds_kernel(const int* __restrict__ seg_ids) {
    int b = blockIdx.x * blockDim.x + threadIdx.x;
    if (b > B_USERS) return;
    int lo = 0, hi = P_POSTS;
    while (lo < hi) {
        int mid = (lo + hi) >> 1;
        if (seg_ids[mid] < b) lo = mid + 1; else hi = mid;
    }
    g_segstart[b] = lo;
}

// ---------------- prep: fp16 W fragments + small transposes ----------------
__global__ void prep_kernel(const float* __restrict__ w3, const float* __restrict__ w4,
                            const float* __restrict__ w5, const float* __restrict__ hw_,
                            const float* __restrict__ w1, const float* __restrict__ w2) {
    int idx = blockIdx.x * 256 + threadIdx.x;
    if (idx < NFRAG * 32) {
        int lane = idx & 31;
        int frag = idx >> 5;
        int Kg; const float* w; int rel;
        if (frag < FRG0)               { Kg = 3; w = w3; rel = frag; }
        else if (frag < FRG0 + FRG1)   { Kg = 4; w = w4; rel = frag - FRG0; }
        else                           { Kg = 5; w = w5; rel = frag - FRG0 - FRG1; }
        int nb = rel / (Kg * DC16);
        int r2 = rel - nb * (Kg * DC16);
        int kk = r2 / DC16;
        int dc = r2 - kk * DC16;
        int n  = lane >> 2;
        int t  = lane & 3;
        int f  = nb * 8 + n;
        float v[4] = {0.f, 0.f, 0.f, 0.f};
        int dk[4] = {2*t, 2*t+1, 2*t+8, 2*t+9};
        if (f < NFILT) {
#pragma unroll
            for (int e = 0; e < 4; ++e) {
                int d = dc * 16 + dk[e];
                if (d < D_EMB) v[e] = __ldg(w + (f * D_EMB + d) * Kg + kk);
            }
        }
        uint2 out;
        out.x = pack_h2(v[0], v[1]);
        out.y = pack_h2(v[2], v[3]);
        g_wf[frag * 32 + lane] = out;
        return;
    }
    int i2 = idx - NFRAG * 32;                 // g_hwt: 300*64
    if (i2 >= 0 && i2 < 300 * 64) {
        int o = i2 & 63; int j = i2 >> 6;
        g_hwt[i2] = __ldg(hw_ + o * 300 + j);
        return;
    }
    int i3 = i2 - 300 * 64;                    // g_w1t: 768*128
    if (i3 >= 0 && i3 < INF_ * 128) {
        int o = i3 & 127; int d = i3 >> 7;
        g_w1t[i3] = __ldg(w1 + o * INF_ + d);
        return;
    }
    int i4 = i3 - INF_ * 128;                  // g_w2t: 128*64
    if (i4 >= 0 && i4 < 128 * 64) {
        int j = i4 & 63; int d = i4 >> 6;
        g_w2t[i4] = __ldg(w2 + j * 128 + d);
    }
}

// ---------------- kernel B: segment-mean -> packed fp16, conv layout ----------------
// grid = (52, B_USERS): rows 50,51 are pad (zeroed). 96 threads; t<75 compute.
__global__ void __launch_bounds__(96)
hist_kernel(const int* __restrict__ tokens, const float* __restrict__ emb) {
    int l = blockIdx.x;
    int b = blockIdx.y;
    int t = threadIdx.x;
    uint2* hq = (uint2*)g_hq;
    size_t rowbase = ((size_t)b * USZ + l * WSTRIDE) >> 1;   // uint2 index

    if (l >= LEN) {                            // pad rows: zero all 156 words
        if (t < WSTRIDE / 2) hq[rowbase + t] = make_uint2(0u, 0u);
        return;
    }
    if (t >= 75) {                             // pad words 150..155
        if (t < 78) hq[rowbase + t] = make_uint2(0u, 0u);
        return;
    }

    int s = g_segstart[b], e = g_segstart[b + 1];
    float4 a = {0.f, 0.f, 0.f, 0.f};
    float4 c = {0.f, 0.f, 0.f, 0.f};
    int p = s;
    for (; p + 3 < e; p += 4) {
        int t0 = __ldg(tokens + p * LEN + l);
        int t1 = __ldg(tokens + (p + 1) * LEN + l);
        int t2 = __ldg(tokens + (p + 2) * LEN + l);
        int t3 = __ldg(tokens + (p + 3) * LEN + l);
        float4 v0 = __ldg((const float4*)(emb + (size_t)t0 * D_EMB) + t);
        float4 v1 = __ldg((const float4*)(emb + (size_t)t1 * D_EMB) + t);
        float4 v2 = __ldg((const float4*)(emb + (size_t)t2 * D_EMB) + t);
        float4 v3 = __ldg((const float4*)(emb + (size_t)t3 * D_EMB) + t);
        a.x += v0.x + v2.x; a.y += v0.y + v2.y; a.z += v0.z + v2.z; a.w += v0.w + v2.w;
        c.x += v1.x + v3.x; c.y += v1.y + v3.y; c.z += v1.z + v3.z; c.w += v1.w + v3.w;
    }
    for (; p < e; ++p) {
        int t0 = __ldg(tokens + p * LEN + l);
        float4 v0 = __ldg((const float4*)(emb + (size_t)t0 * D_EMB) + t);
        a.x += v0.x; a.y += v0.y; a.z += v0.z; a.w += v0.w;
    }
    float sc = 1.0f / (float)max(e - s, 1);
    uint2 w;
    w.x = pack_h2((a.x + c.x) * sc, (a.y + c.y) * sc);
    w.y = pack_h2((a.z + c.z) * sc, (a.w + c.w) * sc);
    hq[rowbase + t] = w;
}

// ---------------- conv job: fp16 single-pass mma, prefetched weights ----------------
template <int CNT>
__device__ __forceinline__ void conv_job(const uint32_t* __restrict__ shq,
                                         int Kg, int gbase, int nb0, int Tg,
                                         const float* __restrict__ bp,
                                         float* __restrict__ sf) {
    int lane = threadIdx.x & 31;
    int g8   = lane >> 2;
    int t    = lane & 3;
    int lr     = lane & 7;
    int sel    = lane >> 3;
    int rowsel = lr + ((sel & 1) << 3);
    int colsel = (sel & 2) << 1;

    float acc[3][CNT][4];
#pragma unroll
    for (int mt = 0; mt < 3; ++mt)
#pragma unroll
        for (int j = 0; j < CNT; ++j)
#pragma unroll
            for (int c = 0; c < 4; ++c) acc[mt][j][c] = 0.f;

    for (int kk = 0; kk < Kg; ++kk) {
        const uint2* fptr = g_wf + (size_t)(gbase + (nb0 * Kg + kk) * DC16) * 32 + lane;
        const size_t jstride = (size_t)(Kg * DC16) * 32;
        int rbase = kk + rowsel;
        uint2 wv[CNT];
#pragma unroll
        for (int j = 0; j < CNT; ++j) wv[j] = __ldg(fptr + j * jstride);

        for (int dc = 0; dc < DC16; ++dc) {
            uint2 wn[CNT];
            if (dc + 1 < DC16) {
#pragma unroll
                for (int j = 0; j < CNT; ++j)
                    wn[j] = __ldg(fptr + j * jstride + (dc + 1) * 32);
            }
            uint32_t ah[3][4];
            int widx = dc * 8 + colsel;
#pragma unroll
            for (int mt = 0; mt < 3; ++mt)
                ldsm4(ah[mt], shq + (mt * 16 + rbase) * WSTRIDE + widx);
#pragma unroll
            for (int j = 0; j < CNT; ++j)
#pragma unroll
                for (int mt = 0; mt < 3; ++mt)
                    MMA_F16(acc[mt][j], ah[mt], wv[j].x, wv[j].y);
#pragma unroll
            for (int j = 0; j < CNT; ++j) wv[j] = wn[j];
        }
    }

#pragma unroll
    for (int j = 0; j < CNT; ++j) {
        float m0 = -1e30f, m1 = -1e30f;
#pragma unroll
        for (int mt = 0; mt < 3; ++mt) {
            int p0 = mt * 16 + g8;
            int p1 = p0 + 8;
            if (p0 < Tg) { m0 = fmaxf(m0, acc[mt][j][0]); m1 = fmaxf(m1, acc[mt][j][1]); }
            if (p1 < Tg) { m0 = fmaxf(m0, acc[mt][j][2]); m1 = fmaxf(m1, acc[mt][j][3]); }
        }
#pragma unroll
        for (int off = 4; off < 32; off <<= 1) {
            m0 = fmaxf(m0, __shfl_xor_sync(0xffffffff, m0, off));
            m1 = fmaxf(m1, __shfl_xor_sync(0xffffffff, m1, off));
        }
        if (g8 == 0) {
            int f0 = (nb0 + j) * 8 + 2 * t;
            if (f0 < NFILT)     sf[f0]     = fmaxf(m0 + __ldg(bp + f0), 0.f);
            if (f0 + 1 < NFILT) sf[f0 + 1] = fmaxf(m1 + __ldg(bp + f0 + 1), 0.f);
        }
    }
}

__device__ __forceinline__ void run_job(const uint32_t* shq,
                                        int g, int nb0, int cnt,
                                        const float* b3, const float* b4,
                                        const float* b5, float* feats_u) {
    int Kg = 3 + g;
    int gbase = (g == 0) ? 0 : ((g == 1) ? FRG0 : (FRG0 + FRG1));
    int Tg = 51 - Kg;
    const float* bp = (g == 0) ? b3 : ((g == 1) ? b4 : b5);
    float* sf = feats_u + g * 100;
    if (cnt == 2) conv_job<2>(shq, Kg, gbase, nb0, Tg, bp, sf);
    else          conv_job<1>(shq, Kg, gbase, nb0, Tg, bp, sf);
}

// ---------------- kernel C: TextCNN via fp16 tensor cores, 1 user / 256 thr ----------------
__global__ void __launch_bounds__(256, 3)
conv_mma_kernel(const float* __restrict__ b3, const float* __restrict__ b4,
                const float* __restrict__ b5, const float* __restrict__ hb_) {
    extern __shared__ uint32_t shw[];           // [hq USZ][feats 304]
    float* feats = (float*)(shw + USZ);
    int tid = threadIdx.x;
    int b   = blockIdx.x;

    {
        uint4* dq = (uint4*)shw;
        const uint4* sq = g_hq + (size_t)b * (USZ / 4);
        for (int i = tid; i < USZ / 4; i += 256) dq[i] = __ldg(sq + i);
    }
    __syncthreads();

    int slot = tid >> 5;
#pragma unroll
    for (int q = 0; q < 4; ++q) {
        Job jb = c_slots[slot][q];
        if (jb.g < 0) continue;
        run_job(shw, jb.g, jb.nb0, jb.cnt, b3, b4, b5, feats);
    }
    __syncthreads();

    // rec GEMM: [300 feats] x [64 outs]
    if (tid < 64) {
        int o = tid;
        float r = __ldg(hb_ + o);
#pragma unroll 4
        for (int j = 0; j < 300; ++j)
            r = fmaf(feats[j], __ldg(g_hwt + j * HID + o), r);
        g_rec[b * HID + o] = r;
    }
}

// ---------------- kernel D: fc_out on root features + final add (TB=8) ----------------
#define TB 8
__global__ void __launch_bounds__(256)
fc_kernel(const float* __restrict__ x, const int* __restrict__ root,
          const float* __restrict__ b1, const float* __restrict__ b2,
          float* __restrict__ out) {
    __shared__ float sx[TB * INF_];
    __shared__ float hh[TB * 128];
    __shared__ int   ridx[TB];
    int tid = threadIdx.x;
    int b0 = blockIdx.x * TB;

    if (tid < TB) ridx[tid] = __ldg(root + b0 + tid);
    __syncthreads();
    for (int i = tid; i < TB * INF_; i += 256) {
        int u = i / INF_; int d = i - u * INF_;
        sx[i] = __ldg(x + (size_t)ridx[u] * INF_ + d);
    }
    __syncthreads();

    {
        int o  = tid & 127;
        int ug = tid >> 7;
        float acc[4] = {0.f, 0.f, 0.f, 0.f};
        for (int d = 0; d < INF_; ++d) {
            float wv = __ldg(g_w1t + d * 128 + o);
#pragma unroll
            for (int uu = 0; uu < 4; ++uu)
                acc[uu] = fmaf(sx[(ug * 4 + uu) * INF_ + d], wv, acc[uu]);
        }
        float bb = __ldg(b1 + o);
#pragma unroll
        for (int uu = 0; uu < 4; ++uu)
            hh[(ug * 4 + uu) * 128 + o] = fmaxf(acc[uu] + bb, 0.f);
    }
    __syncthreads();

    {
        int j = tid & 63;
        int q = tid >> 6;
        int u0 = 2 * q, u1 = 2 * q + 1;
        float a0 = 0.f, a1 = 0.f;
        for (int d = 0; d < 128; ++d) {
            float wv = __ldg(g_w2t + d * 64 + j);
            a0 = fmaf(hh[u0 * 128 + d], wv, a0);
            a1 = fmaf(hh[u1 * 128 + d], wv, a1);
        }
        float bb = __ldg(b2 + j);
        out[(b0 + u0) * HID + j] = a0 + bb + g_rec[(b0 + u0) * HID + j];
        out[(b0 + u1) * HID + j] = a1 + bb + g_rec[(b0 + u1) * HID + j];
    }
}

// ---------------- launch ----------------
extern "C" void kernel_launch(void* const* d_in, const int* in_sizes, int n_in,
                              void* d_out, int out_size) {
    const float* x        = (const float*)d_in[0];
    const int*   root     = (const int*)  d_in[1];
    const int*   tokens   = (const int*)  d_in[2];
    const int*   seg_ids  = (const int*)  d_in[3];
    const float* emb      = (const float*)d_in[4];
    const float* w3 = (const float*)d_in[5];   const float* b3 = (const float*)d_in[6];
    const float* w4 = (const float*)d_in[7];   const float* b4 = (const float*)d_in[8];
    const float* w5 = (const float*)d_in[9];   const float* b5 = (const float*)d_in[10];
    const float* hw = (const float*)d_in[11];  const float* hb = (const float*)d_in[12];
    const float* f1w = (const float*)d_in[13]; const float* f1b = (const float*)d_in[14];
    const float* f2w = (const float*)d_in[15]; const float* f2b = (const float*)d_in[16];
    float* out = (float*)d_out;

    const int conv_smem = (USZ + 304) * (int)sizeof(uint32_t);  // ~33.7 KB
    cudaFuncSetAttribute(conv_mma_kernel, cudaFuncAttributeMaxDynamicSharedMemorySize,
                         conv_smem);

    int prep_threads = NFRAG * 32 + 300 * 64 + INF_ * 128 + 128 * 64;
    seg_bounds_kernel<<<(B_USERS + 1 + 255) / 256, 256>>>(seg_ids);
    prep_kernel<<<(prep_threads + 255) / 256, 256>>>(w3, w4, w5, hw, f1w, f2w);
    {
        dim3 grid(WROWS, B_USERS);               // 52 rows: 50 data + 2 pad
        hist_kernel<<<grid, 96>>>(tokens, emb);
    }
    conv_mma_kernel<<<B_USERS, 256, conv_smem>>>(b3, b4, b5, hb);
    fc_kernel<<<B_USERS / TB, 256>>>(x, root, f1b, f2b, out);
}